// round 17
// baseline (speedup 1.0000x reference)
#include <cuda_runtime.h>
#include <cuda_bf16.h>
#include <math.h>
#include <stdint.h>

// Problem constants
#define NB   8
#define NT   2048
#define NJ   17
#define ND   129
#define NH   8
#define DH   16
#define NBJ  (NB * NJ)        // 136
#define NTOK (NBJ * NT)       // 278528
#define QKVN 384
#define KVSZ 272              // 16x16 kv + 16 ksum per (bj,h)
#define MT   64               // tokens per CTA

// Scratch (device globals: allocation-free rule)
__device__ float g_qkvm[(size_t)NTOK * QKVN];          // phi(q), phi(k), v per token
__device__ float g_kvtab[(size_t)NBJ * NH * KVSZ];     // per (bj,h): kv[16][16], ksum[16]
// Pre-converted bf16 hi/lo weights (row-major [n][k], 256B rows)
__device__ __nv_bfloat16 g_wq_hi[3 * 128 * 128], g_wq_lo[3 * 128 * 128];
__device__ __nv_bfloat16 g_wo_hi[128 * 128],     g_wo_lo[128 * 128];

// ---------------- smem layout (dynamic) ----------------
// bf16 tiles, row stride 272B (136 bf16): ldmatrix conflict-free
// (272 mod 128 = 16 -> 8 rows hit 8 distinct 16B banks).
#define RSB      272
#define OFF_AHI  0                      // A: 64 rows
#define OFF_ALO  (MT * RSB)             // 17408
#define OFF_BHI  (2 * MT * RSB)         // 34816  (B: 64 rows)
#define OFF_BLO  (3 * MT * RSB)         // 52224
#define SMEM_SZ  (4 * MT * RSB)         // 69632 -> 3 CTAs/SM
#define CPAD     132                    // fp32 staging row stride (floats), K3

// ---------------------------- PTX helpers ----------------------------------
__device__ __forceinline__ uint32_t smem_u32(const void* p) {
    uint32_t a;
    asm("{ .reg .u64 t; cvta.to.shared.u64 t, %1; cvt.u32.u64 %0, t; }" : "=r"(a) : "l"(p));
    return a;
}

#define LDSM_X4(r0, r1, r2, r3, addr) \
    asm volatile("ldmatrix.sync.aligned.m8n8.x4.shared.b16 {%0,%1,%2,%3}, [%4];" \
                 : "=r"(r0), "=r"(r1), "=r"(r2), "=r"(r3) : "r"(addr))

#define MMA16816(d, a, b) \
    asm volatile("mma.sync.aligned.m16n8k16.row.col.f32.bf16.bf16.f32 " \
                 "{%0,%1,%2,%3}, {%4,%5,%6,%7}, {%8,%9}, {%0,%1,%2,%3};" \
                 : "+f"((d)[0]), "+f"((d)[1]), "+f"((d)[2]), "+f"((d)[3]) \
                 : "r"((a)[0]), "r"((a)[1]), "r"((a)[2]), "r"((a)[3]), \
                   "r"((b)[0]), "r"((b)[1]))

__device__ __forceinline__ void cvt_hilo(float v, __nv_bfloat16& h, __nv_bfloat16& l) {
    h = __float2bfloat16(v);
    l = __float2bfloat16(v - __bfloat162float(h));
}

// Copy a 64x128 bf16 hi/lo pair (row-major, 256B rows) into the B smem tiles.
__device__ __forceinline__ void copy_b(char* smc, const __nv_bfloat16* __restrict__ hi,
                                       const __nv_bfloat16* __restrict__ lo, int tid) {
#pragma unroll
    for (int it = 0; it < 4; it++) {
        int idx = tid + it * 256;           // 0..1023
        int r = idx >> 4, c = idx & 15;
        *(uint4*)(smc + OFF_BHI + r * RSB + c * 16) =
            __ldg((const uint4*)(hi + r * 128) + c);
        *(uint4*)(smc + OFF_BLO + r * RSB + c * 16) =
            __ldg((const uint4*)(lo + r * 128) + c);
    }
}

// 3-term bf16-split GEMM, warp tile M=16 x N=32, K=128, k-outer fragment
// sharing: 6 LDSM.x4 + 12 MMA per k-step.
__device__ __forceinline__ void mma_split16x32(uint32_t aA_hi, uint32_t aA_lo,
                                               uint32_t aB_hi, uint32_t aB_lo,
                                               float acc[4][4]) {
#pragma unroll 4
    for (int ks = 0; ks < 8; ks++) {
        const uint32_t ko = (uint32_t)ks * 32;
        uint32_t ah[4], al[4];
        LDSM_X4(ah[0], ah[1], ah[2], ah[3], aA_hi + ko);
        LDSM_X4(al[0], al[1], al[2], al[3], aA_lo + ko);
        uint32_t bh[4][2], bl[4][2];
#pragma unroll
        for (int nb = 0; nb < 2; nb++) {
            uint32_t t0, t1, t2, t3;
            LDSM_X4(t0, t1, t2, t3, aB_hi + (uint32_t)nb * (16 * RSB) + ko);
            bh[2 * nb][0] = t0; bh[2 * nb][1] = t1;
            bh[2 * nb + 1][0] = t2; bh[2 * nb + 1][1] = t3;
            LDSM_X4(t0, t1, t2, t3, aB_lo + (uint32_t)nb * (16 * RSB) + ko);
            bl[2 * nb][0] = t0; bl[2 * nb][1] = t1;
            bl[2 * nb + 1][0] = t2; bl[2 * nb + 1][1] = t3;
        }
#pragma unroll
        for (int nt = 0; nt < 4; nt++) {
            MMA16816(acc[nt], ah, bh[nt]);
            MMA16816(acc[nt], al, bh[nt]);
            MMA16816(acc[nt], ah, bl[nt]);
        }
    }
}

// ---------------------------------------------------------------------------
// Kernel 0: one-shot weight conversion fp32 -> bf16 hi/lo.
// ---------------------------------------------------------------------------
__global__ void __launch_bounds__(256)
wconv_kernel(const float* __restrict__ wq, const float* __restrict__ wo) {
    int i = blockIdx.x * 256 + threadIdx.x;
    if (i < 3 * 128 * 128) {
        __nv_bfloat16 h, l;
        cvt_hilo(__ldg(wq + i), h, l);
        g_wq_hi[i] = h; g_wq_lo[i] = l;
    }
    if (i < 128 * 128) {
        __nv_bfloat16 h, l;
        cvt_hilo(__ldg(wo + i), h, l);
        g_wo_hi[i] = h; g_wo_lo[i] = l;
    }
}

// ---------------------------------------------------------------------------
// Kernel 1: qkv GEMM via HMMA. One CTA = 64 tokens; loops 6 (slab, N-half)
// steps against pre-converted weights. 3 CTAs/SM.
// ---------------------------------------------------------------------------
__global__ void __launch_bounds__(256, 3)
qkv_kernel(const float* __restrict__ x, const float* __restrict__ b_qkv) {
    extern __shared__ char smc[];
    const uint32_t sb = smem_u32(smc);
    const int tid = threadIdx.x, lane = tid & 31, wp = tid >> 5;

    const int tok0 = blockIdx.x * MT;
    const int bj = tok0 / NT;
    const int t0 = tok0 - bj * NT;
    const int b = bj / NJ, j = bj - b * NJ;
    const float* xbase = x + ((size_t)(b * NT + t0) * NJ + j) * ND + 1;  // skip time col
    const size_t xstride = (size_t)NJ * ND;

    // A tile: 64 tokens x 128 dims -> hi/lo bf16 (x rows 4B-aligned: scalar ld)
    for (int r = wp; r < MT; r += 8) {
        const float* xr = xbase + (size_t)r * xstride;
#pragma unroll
        for (int cb = 0; cb < 128; cb += 64) {
            int c = cb + 2 * lane;
            float v0 = __ldg(xr + c), v1 = __ldg(xr + c + 1);
            __nv_bfloat16 h0, l0, h1, l1;
            cvt_hilo(v0, h0, l0);
            cvt_hilo(v1, h1, l1);
            uint32_t off = (uint32_t)r * RSB + (uint32_t)c * 2;
            __nv_bfloat162 hp; hp.x = h0; hp.y = h1;
            __nv_bfloat162 lp; lp.x = l0; lp.y = l1;
            *(__nv_bfloat162*)(smc + OFF_AHI + off) = hp;
            *(__nv_bfloat162*)(smc + OFF_ALO + off) = lp;
        }
    }

    // Warp tiling (4m x 2n of 16x32) + per-lane ldmatrix offsets
    const int wm = wp & 3, wn = wp >> 2;
    const int m0 = wm * 16, n0 = wn * 32;
    const uint32_t a_loff = (uint32_t)(lane & 7) * RSB + (uint32_t)((lane >> 3) & 1) * (8 * RSB)
                          + (uint32_t)(lane >> 4) * 16;
    const uint32_t b_loff = (uint32_t)(lane & 7) * RSB + (uint32_t)((lane >> 3) & 1) * 16
                          + (uint32_t)(lane >> 4) * (8 * RSB);
    const uint32_t aA_hi = sb + OFF_AHI + (uint32_t)m0 * RSB + a_loff;
    const uint32_t aA_lo = sb + OFF_ALO + (uint32_t)m0 * RSB + a_loff;
    const uint32_t aB_hi = sb + OFF_BHI + (uint32_t)n0 * RSB + b_loff;
    const uint32_t aB_lo = sb + OFF_BLO + (uint32_t)n0 * RSB + b_loff;

    for (int sh = 0; sh < 6; sh++) {
        const int s = sh >> 1, half = sh & 1;
        if (sh) __syncthreads();  // all warps past previous MMA before B overwrite
        copy_b(smc, g_wq_hi + (size_t)(s * 128 + half * 64) * 128,
                    g_wq_lo + (size_t)(s * 128 + half * 64) * 128, tid);
        __syncthreads();          // A (first iter) + B ready

        float acc[4][4];
#pragma unroll
        for (int nt = 0; nt < 4; nt++)
#pragma unroll
            for (int u = 0; u < 4; u++) acc[nt][u] = 0.0f;

        mma_split16x32(aA_hi, aA_lo, aB_hi, aB_lo, acc);

        // Fragment-direct epilogue: +bias, phi for q/k slabs, store to scratch.
        const int cb = s * 128 + half * 64;
        float2 bv[4];
#pragma unroll
        for (int nt = 0; nt < 4; nt++)
            bv[nt] = __ldg((const float2*)(b_qkv + cb + n0 + nt * 8 + 2 * (lane & 3)));

        const int r0 = m0 + (lane >> 2);
        float* row0 = g_qkvm + (size_t)(tok0 + r0) * QKVN + cb + n0 + 2 * (lane & 3);
        float* row1 = row0 + 8 * QKVN;
#pragma unroll
        for (int nt = 0; nt < 4; nt++) {
            float y00 = acc[nt][0] + bv[nt].x;
            float y01 = acc[nt][1] + bv[nt].y;
            float y10 = acc[nt][2] + bv[nt].x;
            float y11 = acc[nt][3] + bv[nt].y;
            if (s < 2) {  // phi = elu + 1
                y00 = (y00 > 0.0f) ? (y00 + 1.0f) : expf(y00);
                y01 = (y01 > 0.0f) ? (y01 + 1.0f) : expf(y01);
                y10 = (y10 > 0.0f) ? (y10 + 1.0f) : expf(y10);
                y11 = (y11 > 0.0f) ? (y11 + 1.0f) : expf(y11);
            }
            *(float2*)(row0 + nt * 8) = make_float2(y00, y01);
            *(float2*)(row1 + nt * 8) = make_float2(y10, y11);
        }
    }
}

// ---------------------------------------------------------------------------
// Kernel 2: per (bj, h): kv[d][e] = sum_t k_m[t,d]*v[t,e], ksum[d] = sum_t k_m[t,d]
// ---------------------------------------------------------------------------
__global__ void __launch_bounds__(256, 4)
kv_kernel() {
    const int bh = blockIdx.x;
    const int bj = bh >> 3, h = bh & 7;
    const int tid = threadIdx.x;
    const int i = tid >> 4, e = tid & 15;
    __shared__ float ks[16][16];
    __shared__ float vs[16][16];
    float kv = 0.0f, ksm = 0.0f;
    const size_t base = (size_t)bj * NT * QKVN + 128 + h * DH;  // k_m slab offset
    for (int tb = 0; tb < NT; tb += 16) {
#pragma unroll
        for (int r = 0; r < 2; r++) {
            int idx = tid + r * 256;
            int tt = idx >> 5;
            int which = (idx >> 4) & 1;  // 0 -> k_m, 1 -> v (offset +128)
            int li = idx & 15;
            float val = g_qkvm[base + (size_t)(tb + tt) * QKVN + which * 128 + li];
            if (which == 0) ks[tt][li] = val; else vs[tt][li] = val;
        }
        __syncthreads();
#pragma unroll
        for (int tt = 0; tt < 16; tt++) {
            float kk = ks[tt][i];
            kv = fmaf(kk, vs[tt][e], kv);
            if (e == 0) ksm += kk;
        }
        __syncthreads();
    }
    float* dst = g_kvtab + (size_t)bh * KVSZ;
    dst[i * 16 + e] = kv;
    if (e == 0) dst[256 + i] = ksm;
}

// ---------------------------------------------------------------------------
// Kernel 3: agg = (q_m @ kv) / clip(q_m . ksum, EPS) -> bf16 hi/lo A tile,
// y = agg @ w_out^T + b via HMMA (two N-halves, accs in regs), y_time epilogue.
// One CTA = 64 tokens; kv table read via __ldg (L2-resident). 3 CTAs/SM.
// ---------------------------------------------------------------------------
__global__ void __launch_bounds__(256, 3)
out_kernel(const float* __restrict__ b_out, float* __restrict__ out) {
    extern __shared__ char smc[];
    const uint32_t sb = smem_u32(smc);
    const int tid = threadIdx.x, lane = tid & 31, wp = tid >> 5;

    const int tok0 = blockIdx.x * MT;
    const int bj = tok0 / NT;
    const int t0 = tok0 - bj * NT;
    const int b = bj / NJ, j = bj - b * NJ;

    // Phase 1: agg_flat for 64 tokens (4 threads/token, 2 heads each),
    // written as bf16 hi/lo directly into the A tile.
    {
        const int m  = tid >> 2;
        const int hb = (tid & 3) * 2;
        const float* qrow = g_qkvm + (size_t)(tok0 + m) * QKVN;  // q_m at slab 0
#pragma unroll
        for (int hh = 0; hh < 2; hh++) {
            const int h = hb + hh;
            float q[16];
            const float4* q4 = (const float4*)(qrow + h * DH);
#pragma unroll
            for (int u = 0; u < 4; u++) {
                float4 t = __ldg(q4 + u);
                q[4 * u] = t.x; q[4 * u + 1] = t.y; q[4 * u + 2] = t.z; q[4 * u + 3] = t.w;
            }
            const float* kvh = g_kvtab + ((size_t)bj * NH + h) * KVSZ;
            float a[16];
#pragma unroll
            for (int e2 = 0; e2 < 16; e2++) a[e2] = 0.0f;
            float denom = 0.0f;
#pragma unroll
            for (int i = 0; i < 16; i++) {
                const float qi = q[i];
                const float4* kr = (const float4*)(kvh + i * 16);
#pragma unroll
                for (int u = 0; u < 4; u++) {
                    float4 t = __ldg(kr + u);
                    a[4 * u]     = fmaf(qi, t.x, a[4 * u]);
                    a[4 * u + 1] = fmaf(qi, t.y, a[4 * u + 1]);
                    a[4 * u + 2] = fmaf(qi, t.z, a[4 * u + 2]);
                    a[4 * u + 3] = fmaf(qi, t.w, a[4 * u + 3]);
                }
                denom = fmaf(qi, __ldg(kvh + 256 + i), denom);
            }
            denom = fmaxf(denom, 1e-6f);
            const float inv = 1.0f / denom;
#pragma unroll
            for (int e2 = 0; e2 < 16; e2 += 2) {
                __nv_bfloat16 h0, l0, h1, l1;
                cvt_hilo(a[e2] * inv, h0, l0);
                cvt_hilo(a[e2 + 1] * inv, h1, l1);
                uint32_t off = (uint32_t)m * RSB + (uint32_t)(h * DH + e2) * 2;
                __nv_bfloat162 hp; hp.x = h0; hp.y = h1;
                __nv_bfloat162 lp; lp.x = l0; lp.y = l1;
                *(__nv_bfloat162*)(smc + OFF_AHI + off) = hp;
                *(__nv_bfloat162*)(smc + OFF_ALO + off) = lp;
            }
        }
    }
    copy_b(smc, g_wo_hi, g_wo_lo, tid);  // N-half 0, independent of A writes
    __syncthreads();

    const int wm = wp & 3, wn = wp >> 2;
    const int m0 = wm * 16, n0 = wn * 32;
    const uint32_t a_loff = (uint32_t)(lane & 7) * RSB + (uint32_t)((lane >> 3) & 1) * (8 * RSB)
                          + (uint32_t)(lane >> 4) * 16;
    const uint32_t b_loff = (uint32_t)(lane & 7) * RSB + (uint32_t)((lane >> 3) & 1) * 16
                          + (uint32_t)(lane >> 4) * (8 * RSB);
    const uint32_t aA_hi = sb + OFF_AHI + (uint32_t)m0 * RSB + a_loff;
    const uint32_t aA_lo = sb + OFF_ALO + (uint32_t)m0 * RSB + a_loff;
    const uint32_t aB_hi = sb + OFF_BHI + (uint32_t)n0 * RSB + b_loff;
    const uint32_t aB_lo = sb + OFF_BLO + (uint32_t)n0 * RSB + b_loff;

    float acc0[4][4], acc1[4][4];
#pragma unroll
    for (int nt = 0; nt < 4; nt++)
#pragma unroll
        for (int u = 0; u < 4; u++) { acc0[nt][u] = 0.0f; acc1[nt][u] = 0.0f; }

    mma_split16x32(aA_hi, aA_lo, aB_hi, aB_lo, acc0);
    __syncthreads();
    copy_b(smc, g_wo_hi + 64 * 128, g_wo_lo + 64 * 128, tid);  // N-half 1
    __syncthreads();
    mma_split16x32(aA_hi, aA_lo, aB_hi, aB_lo, acc1);
    __syncthreads();  // A no longer needed -> stage over it

    float* Csm = (float*)(smc + OFF_AHI);  // 64 x CPAD floats (33792B <= 34816B)
    {
        const int r = m0 + (lane >> 2);
        const int c = n0 + 2 * (lane & 3);
#pragma unroll
        for (int nt = 0; nt < 4; nt++) {
            *(float2*)(Csm + r * CPAD + c + nt * 8) =
                make_float2(acc0[nt][0], acc0[nt][1]);
            *(float2*)(Csm + (r + 8) * CPAD + c + nt * 8) =
                make_float2(acc0[nt][2], acc0[nt][3]);
            *(float2*)(Csm + r * CPAD + 64 + c + nt * 8) =
                make_float2(acc1[nt][0], acc1[nt][1]);
            *(float2*)(Csm + (r + 8) * CPAD + 64 + c + nt * 8) =
                make_float2(acc1[nt][2], acc1[nt][3]);
        }
    }
    __syncthreads();

    // Per-token epilogue: 4 threads per row, 32 cols each.
    {
        const int m = tid >> 2, quarter = tid & 3;
        const int t = t0 + m;
        const float* crow = Csm + m * CPAD + quarter * 32;
        float* orow = out + ((size_t)(b * NT + t) * NJ + j) * ND;
        float p = 0.0f;
#pragma unroll
        for (int cq = 0; cq < 8; cq++) {
            float4 v = *(const float4*)(crow + 4 * cq);
            float4 bb = __ldg((const float4*)(b_out + quarter * 32 + 4 * cq));
            float y0 = v.x + bb.x, y1 = v.y + bb.y, y2 = v.z + bb.z, y3 = v.w + bb.w;
            p = fmaf(y0, y0, p); p = fmaf(y1, y1, p);
            p = fmaf(y2, y2, p); p = fmaf(y3, y3, p);
            float* od = orow + 1 + quarter * 32 + 4 * cq;
            od[0] = y0; od[1] = y1; od[2] = y2; od[3] = y3;
        }
        p += __shfl_xor_sync(0xffffffffu, p, 1);
        p += __shfl_xor_sync(0xffffffffu, p, 2);
        if (quarter == 0) orow[0] = sqrtf(1.0f + p);
    }
}

// ---------------------------------------------------------------------------
extern "C" void kernel_launch(void* const* d_in, const int* in_sizes, int n_in,
                              void* d_out, int out_size) {
    (void)in_sizes; (void)n_in; (void)out_size;
    const float* x     = (const float*)d_in[0];
    const float* w_qkv = (const float*)d_in[1];
    const float* b_qkv = (const float*)d_in[2];
    const float* w_out = (const float*)d_in[3];
    const float* b_out = (const float*)d_in[4];
    float* out = (float*)d_out;

    cudaFuncSetAttribute(qkv_kernel, cudaFuncAttributeMaxDynamicSharedMemorySize, SMEM_SZ);
    cudaFuncSetAttribute(out_kernel, cudaFuncAttributeMaxDynamicSharedMemorySize, SMEM_SZ);

    wconv_kernel<<<192, 256>>>(w_qkv, w_out);
    qkv_kernel<<<NTOK / MT, 256, SMEM_SZ>>>(x, b_qkv);
    kv_kernel<<<NBJ * NH, 256>>>();
    out_kernel<<<NTOK / MT, 256, SMEM_SZ>>>(b_out, out);
}